// round 11
// baseline (speedup 1.0000x reference)
#include <cuda_runtime.h>
#include <mma.h>
#include <cstdint>
using namespace nvcuda;

#define BB  4
#define TT  2048
#define CC  1024
#define NH_ 16
#define HS_ 64
#define HB_ (BB * NH_)   // 64 (b,h) pairs

// Scratch (device globals — no allocation allowed)
__device__ float g_q[(size_t)BB * NH_ * TT * HS_];   // [B,NH,t,d], tf32
__device__ float g_k[(size_t)BB * NH_ * TT * HS_];   // [B,NH,t,d], tf32
__device__ float g_v[(size_t)BB * NH_ * TT * HS_];   // [B,NH,d,t] TRANSPOSED, tf32
__device__ float g_y[(size_t)BB * TT * CC];          // [B,T,NH,HS], tf32
__device__ float g_xr[(size_t)BB * TT * CC];         // tf32-rounded x
__device__ float g_wr[(size_t)3 * CC * CC];          // tf32-rounded W_attn
__device__ float g_wpr[(size_t)CC * CC];             // tf32-rounded W_proj

__device__ __forceinline__ float ftf(float x) { return wmma::__float_to_tf32(x); }
__device__ __forceinline__ float ex2(float x) {
    float r; asm("ex2.approx.ftz.f32 %0, %1;" : "=f"(r) : "f"(x)); return r;
}
__device__ __forceinline__ unsigned su32(const void* p) {
    return (unsigned)__cvta_generic_to_shared(p);
}
#define CPA16(dst, src) \
    asm volatile("cp.async.cg.shared.global [%0], [%1], 16;" :: "r"(dst), "l"(src))
#define CPCOMMIT() asm volatile("cp.async.commit_group;")
template<int N> __device__ __forceinline__ void cpwait() {
    asm volatile("cp.async.wait_group %0;" :: "n"(N));
}

// Raw tf32 MMA m16n8k8 (lane l: g=l>>2, tg=l&3):
//   A: a0=(g,tg) a1=(g+8,tg) a2=(g,tg+4) a3=(g+8,tg+4)
//   B: b0=(k=tg,n=g) b1=(k=tg+4,n=g)
//   C: c0=(g,2tg) c1=(g,2tg+1) c2=(g+8,2tg) c3=(g+8,2tg+1)
__device__ __forceinline__ void mma_tf32(float* d,
    uint32_t a0, uint32_t a1, uint32_t a2, uint32_t a3,
    uint32_t b0, uint32_t b1)
{
    asm volatile("mma.sync.aligned.m16n8k8.row.col.f32.tf32.tf32.f32 "
        "{%0,%1,%2,%3}, {%4,%5,%6,%7}, {%8,%9}, {%0,%1,%2,%3};"
        : "+f"(d[0]), "+f"(d[1]), "+f"(d[2]), "+f"(d[3])
        : "r"(a0), "r"(a1), "r"(a2), "r"(a3), "r"(b0), "r"(b1));
}

__device__ __forceinline__ void ldsm_x4(uint32_t& r0, uint32_t& r1,
                                        uint32_t& r2, uint32_t& r3, uint32_t addr)
{
    asm volatile("ldmatrix.sync.aligned.m8n8.x4.shared.b16 {%0,%1,%2,%3}, [%4];"
        : "=r"(r0), "=r"(r1), "=r"(r2), "=r"(r3) : "r"(addr));
}

// Per-lane ldmatrix row-address offsets (floats, relative to tile origin).
#define AOFF(S) ((((lane & 7) + ((lane >> 3) & 1) * 8) * (S)) + ((lane >> 4) & 1) * 4)
#define BOFF(S) ((((lane & 7) + ((lane >> 4) & 1) * 8) * (S)) + ((lane >> 3) & 1) * 4)

// ---------------------------------------------------------------------------
// tf32 RN pre-round pass
// ---------------------------------------------------------------------------
__global__ void tf32_round_kernel(const float* __restrict__ src,
                                  float* __restrict__ dst, int n4)
{
    int i = blockIdx.x * blockDim.x + threadIdx.x;
    if (i < n4) {
        float4 v = ((const float4*)src)[i];
        v.x = ftf(v.x); v.y = ftf(v.y); v.z = ftf(v.z); v.w = ftf(v.w);
        ((float4*)dst)[i] = v;
    }
}

// ---------------------------------------------------------------------------
// TF32 GEMM: CTA 128x128, 128 threads = 4 warps (2m x 2n), warp tile 64x64.
// 3-stage cp.async ring, one barrier per K-iter. 2 CTAs/SM overlap barriers.
// Per ks-step per warp: 8 LDSM.x4 -> 32 independent HMMA.
// EPI==0: scatter q/k ([B,NH,t,d]) and v TRANSPOSED ([B,NH,d,t]), ftf-rounded.
// EPI==1: A := g_y, plain fp32 store.
// ---------------------------------------------------------------------------
#define GLD 36
#define GT (128 * GLD)
#define GSTAGE (2 * GT)                 // A+B floats per stage
#define GEMM_SMEM (3 * GSTAGE * 4)      // 110592 B

template<int EPI>
__global__ __launch_bounds__(128, 2) void gemm_tf32_kernel(
    const float* __restrict__ A, const float* __restrict__ W,
    float* __restrict__ out)
{
    extern __shared__ __align__(16) float sh[];   // 3 x [A|B]

    const int tid = threadIdx.x;
    const int bn = blockIdx.x, bm = blockIdx.y;
    const int warp = tid >> 5;
    const int lane = tid & 31;
    const int g = lane >> 2, tg = lane & 3;
    const int wm = warp >> 1, wn = warp & 1;       // 2m x 2n warps

    const int aoff = AOFF(GLD);
    const int boff = BOFF(GLD);

    float c[4][8][4];   // 128 accумulators: i=16-row frag, j=8-col frag
#pragma unroll
    for (int i = 0; i < 4; i++)
#pragma unroll
        for (int j = 0; j < 8; j++)
#pragma unroll
            for (int e = 0; e < 4; e++) c[i][j][e] = 0.0f;

    const float* Asrc = (EPI == 1) ? (const float*)g_y : A;
    const float* Ag = Asrc + (size_t)(bm * 128 + tid) * CC;   // thread = row
    const float* Wg = W + (size_t)(bn * 128 + tid) * CC;
    const uint32_t shb = su32(sh);

    auto fill = [&](int it) {
        int s = it % 3;
        uint32_t da = shb + 4 * (s * GSTAGE + tid * GLD);
        uint32_t db = da + 4 * GT;
        const float* ga = Ag + it * 32;
        const float* gb = Wg + it * 32;
#pragma unroll
        for (int u = 0; u < 8; u++) {
            CPA16(da + u * 16, ga + u * 4);
            CPA16(db + u * 16, gb + u * 4);
        }
        CPCOMMIT();
    };

    fill(0); fill(1);
    const int NIT = CC / 32;
    for (int it = 0; it < NIT; it++) {
        if (it + 1 < NIT) cpwait<1>();
        else              cpwait<0>();
        __syncthreads();
        if (it + 2 < NIT) fill(it + 2);

        const uint32_t asb = shb + 4 * ((it % 3) * GSTAGE);
        const uint32_t bsb = asb + 4 * GT;
#pragma unroll
        for (int ks = 0; ks < 4; ks++) {
            uint32_t af[4][4], bf[4][4];
#pragma unroll
            for (int i = 0; i < 4; i++)
                ldsm_x4(af[i][0], af[i][1], af[i][2], af[i][3],
                        asb + 4 * ((wm * 64 + i * 16) * GLD + ks * 8 + aoff));
#pragma unroll
            for (int j2 = 0; j2 < 4; j2++)
                ldsm_x4(bf[j2][0], bf[j2][1], bf[j2][2], bf[j2][3],
                        bsb + 4 * ((wn * 64 + j2 * 16) * GLD + ks * 8 + boff));
#pragma unroll
            for (int i = 0; i < 4; i++)
#pragma unroll
                for (int j = 0; j < 8; j++)
                    mma_tf32(c[i][j], af[i][0], af[i][1], af[i][2], af[i][3],
                             bf[j >> 1][(j & 1) * 2], bf[j >> 1][(j & 1) * 2 + 1]);
        }
    }

#pragma unroll
    for (int i = 0; i < 4; i++) {
        int mA = bm * 128 + wm * 64 + i * 16 + g;
        int mB = mA + 8;
#pragma unroll
        for (int j = 0; j < 8; j++) {
            int n = bn * 128 + wn * 64 + j * 8 + 2 * tg;
            if (EPI == 0) {
                int which = n >> 10;
                int cc = n & 1023;
                int head = cc >> 6, d = cc & 63;
                int bA = mA >> 11, tA = mA & 2047;
                int bB = mB >> 11, tB = mB & 2047;
                if (which == 2) {   // v: transposed [B,NH,d,t]
                    float* base = g_v + ((size_t)(bA * NH_ + head) * HS_) * TT;
                    base[(size_t)(d    ) * TT + tA] = ftf(c[i][j][0]);
                    base[(size_t)(d + 1) * TT + tA] = ftf(c[i][j][1]);
                    float* baseB = g_v + ((size_t)(bB * NH_ + head) * HS_) * TT;
                    baseB[(size_t)(d    ) * TT + tB] = ftf(c[i][j][2]);
                    baseB[(size_t)(d + 1) * TT + tB] = ftf(c[i][j][3]);
                } else {
                    float* dst = (which == 0) ? g_q : g_k;
                    *(float2*)&dst[(((size_t)(bA * NH_ + head)) * TT + tA) * HS_ + d] =
                        make_float2(ftf(c[i][j][0]), ftf(c[i][j][1]));
                    *(float2*)&dst[(((size_t)(bB * NH_ + head)) * TT + tB) * HS_ + d] =
                        make_float2(ftf(c[i][j][2]), ftf(c[i][j][3]));
                }
            } else {
                *(float2*)&out[(size_t)mA * CC + n] = make_float2(c[i][j][0], c[i][j][1]);
                *(float2*)&out[(size_t)mB * CC + n] = make_float2(c[i][j][2], c[i][j][3]);
            }
        }
    }
}

// ---------------------------------------------------------------------------
// Flash attention (unchanged from R10): register-resident mma.sync + ldmatrix,
// one barrier per chunk.
// ---------------------------------------------------------------------------
#define FLD 68
#define FKV (64 * FLD)
#define FSS (128 * FLD)
#define FLASH_SMEM ((4 * FKV + FSS) * 4)

__global__ __launch_bounds__(256) void flash_mma_kernel()
{
    extern __shared__ __align__(16) float sh[];
    float* Ss = sh + 4 * FKV;

    const int qt = gridDim.x - 1 - blockIdx.x;   // heavy tiles first
    const int hb = blockIdx.y;
    const int tid = threadIdx.x;
    const int warp = tid >> 5;
    const int lane = tid & 31;
    const int g = lane >> 2, tg = lane & 3;
    const int lr = tid >> 2, lq = (tid & 3) * 16;
    const int rq = tid >> 1, hq = tid & 1;

    const int aoff = AOFF(FLD);
    const int boff = BOFF(FLD);
    const int nc = 2 * qt + 2;

    auto issue = [&](int c, int s) {
        const float* kp = g_k + ((size_t)hb * TT + c * 64 + lr) * HS_ + lq;
        const float* vp = g_v + ((size_t)hb * HS_ + lr) * TT + c * 64 + lq;  // [d][t]
        unsigned dk = su32(sh + s * FKV + lr * FLD + lq);
        unsigned dv = su32(sh + (2 + s) * FKV + lr * FLD + lq);
#pragma unroll
        for (int u = 0; u < 4; u++) {
            CPA16(dk + u * 16, kp + u * 4);
            CPA16(dv + u * 16, vp + u * 4);
        }
        CPCOMMIT();
    };

    issue(0, 0);

    // ---- stage Q through own Ss band, pull A-frags via ldmatrix ----
    const float* qp = g_q + ((size_t)hb * TT + qt * 128) * HS_;
    const float qs = 0.125f * 1.44269504f;
#pragma unroll
    for (int u = 0; u < 8; u++) {
        float4 v = *(const float4*)(qp + rq * 64 + hq * 32 + u * 4);
        v.x = ftf(v.x * qs); v.y = ftf(v.y * qs);
        v.z = ftf(v.z * qs); v.w = ftf(v.w * qs);
        *(float4*)&Ss[rq * FLD + hq * 32 + u * 4] = v;
    }
    __syncwarp();
    const uint32_t ssb = su32(Ss);
    uint32_t qa[8][4];
#pragma unroll
    for (int kc = 0; kc < 8; kc++)
        ldsm_x4(qa[kc][0], qa[kc][1], qa[kc][2], qa[kc][3],
                ssb + 4 * ((16 * warp) * FLD + 8 * kc + aoff));
    __syncwarp();

    float o[8][4];
#pragma unroll
    for (int j = 0; j < 8; j++)
#pragma unroll
        for (int e = 0; e < 4; e++) o[j][e] = 0.0f;
    float m0 = -1e30f, m1 = -1e30f, l0 = 0.0f, l1 = 0.0f;

    for (int c = 0; c < nc; c++) {
        cpwait<0>();
        __syncthreads();
        if (c + 1 < nc) issue(c + 1, (c + 1) & 1);

        const uint32_t ksb = su32(sh + (c & 1) * FKV);
        const uint32_t vsb = su32(sh + (2 + (c & 1)) * FKV);

        const int lim = (c >= 2 * qt) ? (16 * warp + 15 - 64 * (c - 2 * qt)) : 127;
        if (lim >= 0) {
            const int j2max = min(3, lim >> 4);
            const int jmax = min(7, 2 * j2max + 1);

            float s[8][4];
#pragma unroll
            for (int j = 0; j < 8; j++)
#pragma unroll
                for (int e = 0; e < 4; e++) s[j][e] = 0.0f;
#pragma unroll
            for (int kc = 0; kc < 8; kc++) {
#pragma unroll
                for (int j2 = 0; j2 < 4; j2++) {
                    if (j2 > j2max) break;
                    uint32_t b0, b1, b2, b3;
                    ldsm_x4(b0, b1, b2, b3,
                            ksb + 4 * ((16 * j2) * FLD + 8 * kc + boff));
                    mma_tf32(s[2 * j2], qa[kc][0], qa[kc][1], qa[kc][2], qa[kc][3], b0, b1);
                    mma_tf32(s[2 * j2 + 1], qa[kc][0], qa[kc][1], qa[kc][2], qa[kc][3], b2, b3);
                }
            }

            if (c >= 2 * qt) {
                const int kb = 64 * (c - 2 * qt);
                const int row0 = 16 * warp + g, row1 = row0 + 8;
#pragma unroll
                for (int j = 0; j < 8; j++) {
                    if (j > jmax) break;
                    int col = kb + 8 * j + 2 * tg;
                    if (col     > row0) s[j][0] = -1e30f;
                    if (col + 1 > row0) s[j][1] = -1e30f;
                    if (col     > row1) s[j][2] = -1e30f;
                    if (col + 1 > row1) s[j][3] = -1e30f;
                }
            }

            float rm0 = -1e30f, rm1 = -1e30f;
#pragma unroll
            for (int j = 0; j < 8; j++) {
                if (j > jmax) break;
                rm0 = fmaxf(rm0, fmaxf(s[j][0], s[j][1]));
                rm1 = fmaxf(rm1, fmaxf(s[j][2], s[j][3]));
            }
            rm0 = fmaxf(rm0, __shfl_xor_sync(0xffffffffu, rm0, 1));
            rm0 = fmaxf(rm0, __shfl_xor_sync(0xffffffffu, rm0, 2));
            rm1 = fmaxf(rm1, __shfl_xor_sync(0xffffffffu, rm1, 1));
            rm1 = fmaxf(rm1, __shfl_xor_sync(0xffffffffu, rm1, 2));
            float mn0 = fmaxf(m0, rm0), mn1 = fmaxf(m1, rm1);
            float corr0 = ex2(m0 - mn0), corr1 = ex2(m1 - mn1);
            float rs0 = 0.0f, rs1 = 0.0f;
#pragma unroll
            for (int j = 0; j < 8; j++) {
                if (j > jmax) break;
                s[j][0] = ex2(s[j][0] - mn0); rs0 += s[j][0];
                s[j][1] = ex2(s[j][1] - mn0); rs0 += s[j][1];
                s[j][2] = ex2(s[j][2] - mn1); rs1 += s[j][2];
                s[j][3] = ex2(s[j][3] - mn1); rs1 += s[j][3];
            }
            rs0 += __shfl_xor_sync(0xffffffffu, rs0, 1);
            rs0 += __shfl_xor_sync(0xffffffffu, rs0, 2);
            rs1 += __shfl_xor_sync(0xffffffffu, rs1, 1);
            rs1 += __shfl_xor_sync(0xffffffffu, rs1, 2);
            l0 = l0 * corr0 + rs0; m0 = mn0;
            l1 = l1 * corr1 + rs1; m1 = mn1;
#pragma unroll
            for (int j = 0; j < 8; j++) {
                o[j][0] *= corr0; o[j][1] *= corr0;
                o[j][2] *= corr1; o[j][3] *= corr1;
            }

            const int pr0 = (16 * warp + g) * FLD, pr1 = (16 * warp + g + 8) * FLD;
#pragma unroll
            for (int j = 0; j < 8; j++) {
                if (j > jmax) break;
                *(float2*)&Ss[pr0 + 8 * j + 2 * tg] =
                    make_float2(ftf(s[j][0]), ftf(s[j][1]));
                *(float2*)&Ss[pr1 + 8 * j + 2 * tg] =
                    make_float2(ftf(s[j][2]), ftf(s[j][3]));
            }
            __syncwarp();

#pragma unroll
            for (int kc = 0; kc < 8; kc++) {
                if (kc > jmax) break;
                uint32_t pa0, pa1, pa2, pa3;
                ldsm_x4(pa0, pa1, pa2, pa3,
                        ssb + 4 * ((16 * warp) * FLD + 8 * kc + aoff));
#pragma unroll
                for (int j2 = 0; j2 < 4; j2++) {
                    uint32_t b0, b1, b2, b3;
                    ldsm_x4(b0, b1, b2, b3,
                            vsb + 4 * ((16 * j2) * FLD + 8 * kc + boff));
                    mma_tf32(o[2 * j2], pa0, pa1, pa2, pa3, b0, b1);
                    mma_tf32(o[2 * j2 + 1], pa0, pa1, pa2, pa3, b2, b3);
                }
            }
            __syncwarp();
        }
    }

    const float inv0 = 1.0f / l0, inv1 = 1.0f / l1;
    const int b_ = hb >> 4, head = hb & 15;
    const int t0 = qt * 128 + 16 * warp + g, t1 = t0 + 8;
    float* y0 = g_y + (((size_t)(b_ * TT + t0)) * NH_ + head) * HS_;
    float* y1 = g_y + (((size_t)(b_ * TT + t1)) * NH_ + head) * HS_;
#pragma unroll
    for (int j = 0; j < 8; j++) {
        *(float2*)&y0[8 * j + 2 * tg] =
            make_float2(ftf(o[j][0] * inv0), ftf(o[j][1] * inv0));
        *(float2*)&y1[8 * j + 2 * tg] =
            make_float2(ftf(o[j][2] * inv1), ftf(o[j][3] * inv1));
    }
}

// ---------------------------------------------------------------------------
extern "C" void kernel_launch(void* const* d_in, const int* in_sizes, int n_in,
                              void* d_out, int out_size)
{
    const float* x      = (const float*)d_in[0];  // [B,T,C]
    const float* W_attn = (const float*)d_in[1];  // [3C,C]
    const float* W_proj = (const float*)d_in[2];  // [C,C]
    // d_in[3..6] feed a discarded branch — skipped.
    float* out = (float*)d_out;                   // [B,T,C] fp32

    cudaFuncSetAttribute(gemm_tf32_kernel<0>,
                         cudaFuncAttributeMaxDynamicSharedMemorySize, GEMM_SMEM);
    cudaFuncSetAttribute(gemm_tf32_kernel<1>,
                         cudaFuncAttributeMaxDynamicSharedMemorySize, GEMM_SMEM);
    cudaFuncSetAttribute(flash_mma_kernel,
                         cudaFuncAttributeMaxDynamicSharedMemorySize, FLASH_SMEM);

    float* xr;  cudaGetSymbolAddress((void**)&xr,  g_xr);
    float* wr;  cudaGetSymbolAddress((void**)&wr,  g_wr);
    float* wpr; cudaGetSymbolAddress((void**)&wpr, g_wpr);

    const int n4x = BB * TT * CC / 4;
    const int n4w = 3 * CC * CC / 4;
    const int n4p = CC * CC / 4;
    tf32_round_kernel<<<(n4x + 255) / 256, 256>>>(x, xr, n4x);
    tf32_round_kernel<<<(n4w + 255) / 256, 256>>>(W_attn, wr, n4w);
    tf32_round_kernel<<<(n4p + 255) / 256, 256>>>(W_proj, wpr, n4p);

    gemm_tf32_kernel<0><<<dim3(3 * CC / 128, BB * TT / 128), 128, GEMM_SMEM>>>(xr, wr, nullptr);
    flash_mma_kernel<<<dim3(TT / 128, HB_), 256, FLASH_SMEM>>>();
    gemm_tf32_kernel<1><<<dim3(CC / 128, BB * TT / 128), 128, GEMM_SMEM>>>(xr, wpr, out);
}

// round 12
// speedup vs baseline: 1.1923x; 1.1923x over previous
#include <cuda_runtime.h>
#include <mma.h>
#include <cstdint>
using namespace nvcuda;

#define BB  4
#define TT  2048
#define CC  1024
#define NH_ 16
#define HS_ 64
#define HB_ (BB * NH_)   // 64 (b,h) pairs

// Scratch (device globals — no allocation allowed)
__device__ float g_q[(size_t)BB * NH_ * TT * HS_];   // [B,NH,t,d], tf32
__device__ float g_k[(size_t)BB * NH_ * TT * HS_];   // [B,NH,t,d], tf32
__device__ float g_v[(size_t)BB * NH_ * TT * HS_];   // [B,NH,d,t] TRANSPOSED, tf32
__device__ float g_y[(size_t)BB * TT * CC];          // [B,T,NH,HS], tf32

__device__ __forceinline__ float ftf(float x) { return wmma::__float_to_tf32(x); }
__device__ __forceinline__ float4 ftf4(float4 v) {
    return make_float4(ftf(v.x), ftf(v.y), ftf(v.z), ftf(v.w));
}
__device__ __forceinline__ float ex2(float x) {
    float r; asm("ex2.approx.ftz.f32 %0, %1;" : "=f"(r) : "f"(x)); return r;
}
__device__ __forceinline__ unsigned su32(const void* p) {
    return (unsigned)__cvta_generic_to_shared(p);
}
#define CPA16(dst, src) \
    asm volatile("cp.async.cg.shared.global [%0], [%1], 16;" :: "r"(dst), "l"(src))
#define CPCOMMIT() asm volatile("cp.async.commit_group;")
template<int N> __device__ __forceinline__ void cpwait() {
    asm volatile("cp.async.wait_group %0;" :: "n"(N));
}

// Raw tf32 MMA m16n8k8 (lane l: g=l>>2, tg=l&3):
//   A: a0=(g,tg) a1=(g+8,tg) a2=(g,tg+4) a3=(g+8,tg+4)
//   B: b0=(k=tg,n=g) b1=(k=tg+4,n=g)
//   C: c0=(g,2tg) c1=(g,2tg+1) c2=(g+8,2tg) c3=(g+8,2tg+1)
__device__ __forceinline__ void mma_tf32(float* d,
    uint32_t a0, uint32_t a1, uint32_t a2, uint32_t a3,
    uint32_t b0, uint32_t b1)
{
    asm volatile("mma.sync.aligned.m16n8k8.row.col.f32.tf32.tf32.f32 "
        "{%0,%1,%2,%3}, {%4,%5,%6,%7}, {%8,%9}, {%0,%1,%2,%3};"
        : "+f"(d[0]), "+f"(d[1]), "+f"(d[2]), "+f"(d[3])
        : "r"(a0), "r"(a1), "r"(a2), "r"(a3), "r"(b0), "r"(b1));
}

__device__ __forceinline__ void ldsm_x4(uint32_t& r0, uint32_t& r1,
                                        uint32_t& r2, uint32_t& r3, uint32_t addr)
{
    asm volatile("ldmatrix.sync.aligned.m8n8.x4.shared.b16 {%0,%1,%2,%3}, [%4];"
        : "=r"(r0), "=r"(r1), "=r"(r2), "=r"(r3) : "r"(addr));
}

// Per-lane ldmatrix row-address offsets (floats, relative to tile origin).
#define AOFF(S) ((((lane & 7) + ((lane >> 3) & 1) * 8) * (S)) + ((lane >> 4) & 1) * 4)
#define BOFF(S) ((((lane & 7) + ((lane >> 4) & 1) * 8) * (S)) + ((lane >> 3) & 1) * 4)

// ---------------------------------------------------------------------------
// TF32 GEMM (R8 config — best measured): C = A @ W^T.
// Naive LDG + STS (ptxas pipelines the loads), tf32 conversion at STS time,
// Block 128x128, BK=32, 256 threads = 8 warps (2m x 4n), warp tile 64x32,
// static smem, 2 CTAs/SM.
// EPI==0: scatter q/k ([B,NH,t,d]) and v TRANSPOSED ([B,NH,d,t]), ftf-rounded.
// EPI==1: A := g_y, plain fp32 store.
// ---------------------------------------------------------------------------
template<int EPI>
__global__ __launch_bounds__(256, 2) void gemm_tf32_kernel(
    const float* __restrict__ A, const float* __restrict__ W,
    float* __restrict__ out)
{
    __shared__ __align__(16) float As[128][36];
    __shared__ __align__(16) float Bs[128][36];

    const int tid = threadIdx.x;
    const int bn = blockIdx.x, bm = blockIdx.y;
    const int warp = tid >> 5;
    const int lane = tid & 31;
    const int g = lane >> 2, tg = lane & 3;
    const int wm = warp >> 2, wn = warp & 3;       // 2m x 4n warps
    const int lrow = tid >> 1, lcol = (tid & 1) * 16;

    const int aoff = AOFF(36);
    const int boff = BOFF(36);

    float c[4][4][4];
#pragma unroll
    for (int i = 0; i < 4; i++)
#pragma unroll
        for (int j = 0; j < 4; j++)
#pragma unroll
            for (int e = 0; e < 4; e++) c[i][j][e] = 0.0f;

    const float* Asrc = (EPI == 1) ? (const float*)g_y : A;
    const float* Ab = Asrc + (size_t)(bm * 128 + lrow) * CC + lcol;
    const float* Wb = W + (size_t)(bn * 128 + lrow) * CC + lcol;

    const uint32_t asb = su32(&As[0][0]);
    const uint32_t bsb = su32(&Bs[0][0]);

    for (int k0 = 0; k0 < CC; k0 += 32) {
        float4 a[4], b[4];
#pragma unroll
        for (int u = 0; u < 4; u++) {
            a[u] = *(const float4*)(Ab + k0 + u * 4);
            b[u] = *(const float4*)(Wb + k0 + u * 4);
        }
        __syncthreads();
#pragma unroll
        for (int u = 0; u < 4; u++) {
            *(float4*)&As[lrow][lcol + u * 4] = ftf4(a[u]);
            *(float4*)&Bs[lrow][lcol + u * 4] = ftf4(b[u]);
        }
        __syncthreads();
#pragma unroll
        for (int ks = 0; ks < 4; ks++) {
            uint32_t af[4][4], bf[2][4];
#pragma unroll
            for (int i = 0; i < 4; i++)
                ldsm_x4(af[i][0], af[i][1], af[i][2], af[i][3],
                        asb + 4 * ((wm * 64 + i * 16) * 36 + ks * 8 + aoff));
#pragma unroll
            for (int j2 = 0; j2 < 2; j2++)
                ldsm_x4(bf[j2][0], bf[j2][1], bf[j2][2], bf[j2][3],
                        bsb + 4 * ((wn * 32 + j2 * 16) * 36 + ks * 8 + boff));
#pragma unroll
            for (int i = 0; i < 4; i++)
#pragma unroll
                for (int j = 0; j < 4; j++)
                    mma_tf32(c[i][j], af[i][0], af[i][1], af[i][2], af[i][3],
                             bf[j >> 1][(j & 1) * 2], bf[j >> 1][(j & 1) * 2 + 1]);
        }
    }

    // Epilogue: c layout c0=(g,2tg) c1=(g,2tg+1) c2=(g+8,2tg) c3=(g+8,2tg+1)
#pragma unroll
    for (int i = 0; i < 4; i++) {
        int mA = bm * 128 + wm * 64 + i * 16 + g;
        int mB = mA + 8;
#pragma unroll
        for (int j = 0; j < 4; j++) {
            int n = bn * 128 + wn * 32 + j * 8 + 2 * tg;
            if (EPI == 0) {
                int which = n >> 10;
                int cc = n & 1023;
                int head = cc >> 6, d = cc & 63;
                int bA = mA >> 11, tA = mA & 2047;
                int bB = mB >> 11, tB = mB & 2047;
                if (which == 2) {   // v: transposed [B,NH,d,t]
                    float* base = g_v + ((size_t)(bA * NH_ + head) * HS_) * TT;
                    base[(size_t)(d    ) * TT + tA] = ftf(c[i][j][0]);
                    base[(size_t)(d + 1) * TT + tA] = ftf(c[i][j][1]);
                    float* baseB = g_v + ((size_t)(bB * NH_ + head) * HS_) * TT;
                    baseB[(size_t)(d    ) * TT + tB] = ftf(c[i][j][2]);
                    baseB[(size_t)(d + 1) * TT + tB] = ftf(c[i][j][3]);
                } else {
                    float* dst = (which == 0) ? g_q : g_k;
                    *(float2*)&dst[(((size_t)(bA * NH_ + head)) * TT + tA) * HS_ + d] =
                        make_float2(ftf(c[i][j][0]), ftf(c[i][j][1]));
                    *(float2*)&dst[(((size_t)(bB * NH_ + head)) * TT + tB) * HS_ + d] =
                        make_float2(ftf(c[i][j][2]), ftf(c[i][j][3]));
                }
            } else {
                *(float2*)&out[(size_t)mA * CC + n] = make_float2(c[i][j][0], c[i][j][1]);
                *(float2*)&out[(size_t)mB * CC + n] = make_float2(c[i][j][2], c[i][j][3]);
            }
        }
    }
}

// ---------------------------------------------------------------------------
// Flash attention (R10 — best measured): register-resident mma.sync +
// ldmatrix, one barrier per chunk, V^T B-frags.
// ---------------------------------------------------------------------------
#define FLD 68
#define FKV (64 * FLD)
#define FSS (128 * FLD)
#define FLASH_SMEM ((4 * FKV + FSS) * 4)

__global__ __launch_bounds__(256) void flash_mma_kernel()
{
    extern __shared__ __align__(16) float sh[];
    float* Ss = sh + 4 * FKV;

    const int qt = gridDim.x - 1 - blockIdx.x;   // heavy tiles first
    const int hb = blockIdx.y;
    const int tid = threadIdx.x;
    const int warp = tid >> 5;
    const int lane = tid & 31;
    const int g = lane >> 2, tg = lane & 3;
    const int lr = tid >> 2, lq = (tid & 3) * 16;
    const int rq = tid >> 1, hq = tid & 1;

    const int aoff = AOFF(FLD);
    const int boff = BOFF(FLD);
    const int nc = 2 * qt + 2;

    auto issue = [&](int c, int s) {
        const float* kp = g_k + ((size_t)hb * TT + c * 64 + lr) * HS_ + lq;
        const float* vp = g_v + ((size_t)hb * HS_ + lr) * TT + c * 64 + lq;  // [d][t]
        unsigned dk = su32(sh + s * FKV + lr * FLD + lq);
        unsigned dv = su32(sh + (2 + s) * FKV + lr * FLD + lq);
#pragma unroll
        for (int u = 0; u < 4; u++) {
            CPA16(dk + u * 16, kp + u * 4);
            CPA16(dv + u * 16, vp + u * 4);
        }
        CPCOMMIT();
    };

    issue(0, 0);

    // ---- stage Q through own Ss band, pull A-frags via ldmatrix ----
    const float* qp = g_q + ((size_t)hb * TT + qt * 128) * HS_;
    const float qs = 0.125f * 1.44269504f;
#pragma unroll
    for (int u = 0; u < 8; u++) {
        float4 v = *(const float4*)(qp + rq * 64 + hq * 32 + u * 4);
        v.x = ftf(v.x * qs); v.y = ftf(v.y * qs);
        v.z = ftf(v.z * qs); v.w = ftf(v.w * qs);
        *(float4*)&Ss[rq * FLD + hq * 32 + u * 4] = v;
    }
    __syncwarp();
    const uint32_t ssb = su32(Ss);
    uint32_t qa[8][4];
#pragma unroll
    for (int kc = 0; kc < 8; kc++)
        ldsm_x4(qa[kc][0], qa[kc][1], qa[kc][2], qa[kc][3],
                ssb + 4 * ((16 * warp) * FLD + 8 * kc + aoff));
    __syncwarp();

    float o[8][4];
#pragma unroll
    for (int j = 0; j < 8; j++)
#pragma unroll
        for (int e = 0; e < 4; e++) o[j][e] = 0.0f;
    float m0 = -1e30f, m1 = -1e30f, l0 = 0.0f, l1 = 0.0f;

    for (int c = 0; c < nc; c++) {
        cpwait<0>();
        __syncthreads();
        if (c + 1 < nc) issue(c + 1, (c + 1) & 1);

        const uint32_t ksb = su32(sh + (c & 1) * FKV);
        const uint32_t vsb = su32(sh + (2 + (c & 1)) * FKV);

        const int lim = (c >= 2 * qt) ? (16 * warp + 15 - 64 * (c - 2 * qt)) : 127;
        if (lim >= 0) {
            const int j2max = min(3, lim >> 4);
            const int jmax = min(7, 2 * j2max + 1);

            float s[8][4];
#pragma unroll
            for (int j = 0; j < 8; j++)
#pragma unroll
                for (int e = 0; e < 4; e++) s[j][e] = 0.0f;
#pragma unroll
            for (int kc = 0; kc < 8; kc++) {
#pragma unroll
                for (int j2 = 0; j2 < 4; j2++) {
                    if (j2 > j2max) break;
                    uint32_t b0, b1, b2, b3;
                    ldsm_x4(b0, b1, b2, b3,
                            ksb + 4 * ((16 * j2) * FLD + 8 * kc + boff));
                    mma_tf32(s[2 * j2], qa[kc][0], qa[kc][1], qa[kc][2], qa[kc][3], b0, b1);
                    mma_tf32(s[2 * j2 + 1], qa[kc][0], qa[kc][1], qa[kc][2], qa[kc][3], b2, b3);
                }
            }

            if (c >= 2 * qt) {
                const int kb = 64 * (c - 2 * qt);
                const int row0 = 16 * warp + g, row1 = row0 + 8;
#pragma unroll
                for (int j = 0; j < 8; j++) {
                    if (j > jmax) break;
                    int col = kb + 8 * j + 2 * tg;
                    if (col     > row0) s[j][0] = -1e30f;
                    if (col + 1 > row0) s[j][1] = -1e30f;
                    if (col     > row1) s[j][2] = -1e30f;
                    if (col + 1 > row1) s[j][3] = -1e30f;
                }
            }

            float rm0 = -1e30f, rm1 = -1e30f;
#pragma unroll
            for (int j = 0; j < 8; j++) {
                if (j > jmax) break;
                rm0 = fmaxf(rm0, fmaxf(s[j][0], s[j][1]));
                rm1 = fmaxf(rm1, fmaxf(s[j][2], s[j][3]));
            }
            rm0 = fmaxf(rm0, __shfl_xor_sync(0xffffffffu, rm0, 1));
            rm0 = fmaxf(rm0, __shfl_xor_sync(0xffffffffu, rm0, 2));
            rm1 = fmaxf(rm1, __shfl_xor_sync(0xffffffffu, rm1, 1));
            rm1 = fmaxf(rm1, __shfl_xor_sync(0xffffffffu, rm1, 2));
            float mn0 = fmaxf(m0, rm0), mn1 = fmaxf(m1, rm1);
            float corr0 = ex2(m0 - mn0), corr1 = ex2(m1 - mn1);
            float rs0 = 0.0f, rs1 = 0.0f;
#pragma unroll
            for (int j = 0; j < 8; j++) {
                if (j > jmax) break;
                s[j][0] = ex2(s[j][0] - mn0); rs0 += s[j][0];
                s[j][1] = ex2(s[j][1] - mn0); rs0 += s[j][1];
                s[j][2] = ex2(s[j][2] - mn1); rs1 += s[j][2];
                s[j][3] = ex2(s[j][3] - mn1); rs1 += s[j][3];
            }
            rs0 += __shfl_xor_sync(0xffffffffu, rs0, 1);
            rs0 += __shfl_xor_sync(0xffffffffu, rs0, 2);
            rs1 += __shfl_xor_sync(0xffffffffu, rs1, 1);
            rs1 += __shfl_xor_sync(0xffffffffu, rs1, 2);
            l0 = l0 * corr0 + rs0; m0 = mn0;
            l1 = l1 * corr1 + rs1; m1 = mn1;
#pragma unroll
            for (int j = 0; j < 8; j++) {
                o[j][0] *= corr0; o[j][1] *= corr0;
                o[j][2] *= corr1; o[j][3] *= corr1;
            }

            const int pr0 = (16 * warp + g) * FLD, pr1 = (16 * warp + g + 8) * FLD;
#pragma unroll
            for (int j = 0; j < 8; j++) {
                if (j > jmax) break;
                *(float2*)&Ss[pr0 + 8 * j + 2 * tg] =
                    make_float2(ftf(s[j][0]), ftf(s[j][1]));
                *(float2*)&Ss[pr1 + 8 * j + 2 * tg] =
                    make_float2(ftf(s[j][2]), ftf(s[j][3]));
            }
            __syncwarp();

#pragma unroll
            for (int kc = 0; kc < 8; kc++) {
                if (kc > jmax) break;
                uint32_t pa0, pa1, pa2, pa3;
                ldsm_x4(pa0, pa1, pa2, pa3,
                        ssb + 4 * ((16 * warp) * FLD + 8 * kc + aoff));
#pragma unroll
                for (int j2 = 0; j2 < 4; j2++) {
                    uint32_t b0, b1, b2, b3;
                    ldsm_x4(b0, b1, b2, b3,
                            vsb + 4 * ((16 * j2) * FLD + 8 * kc + boff));
                    mma_tf32(o[2 * j2], pa0, pa1, pa2, pa3, b0, b1);
                    mma_tf32(o[2 * j2 + 1], pa0, pa1, pa2, pa3, b2, b3);
                }
            }
            __syncwarp();
        }
    }

    // ---- write O (tf32-rounded, feeds proj) in [B,T,NH,HS] ----
    const float inv0 = 1.0f / l0, inv1 = 1.0f / l1;
    const int b_ = hb >> 4, head = hb & 15;
    const int t0 = qt * 128 + 16 * warp + g, t1 = t0 + 8;
    float* y0 = g_y + (((size_t)(b_ * TT + t0)) * NH_ + head) * HS_;
    float* y1 = g_y + (((size_t)(b_ * TT + t1)) * NH_ + head) * HS_;
#pragma unroll
    for (int j = 0; j < 8; j++) {
        *(float2*)&y0[8 * j + 2 * tg] =
            make_float2(ftf(o[j][0] * inv0), ftf(o[j][1] * inv0));
        *(float2*)&y1[8 * j + 2 * tg] =
            make_float2(ftf(o[j][2] * inv1), ftf(o[j][3] * inv1));
    }
}

// ---------------------------------------------------------------------------
extern "C" void kernel_launch(void* const* d_in, const int* in_sizes, int n_in,
                              void* d_out, int out_size)
{
    const float* x      = (const float*)d_in[0];  // [B,T,C]
    const float* W_attn = (const float*)d_in[1];  // [3C,C]
    const float* W_proj = (const float*)d_in[2];  // [C,C]
    // d_in[3..6] feed a discarded branch — skipped.
    float* out = (float*)d_out;                   // [B,T,C] fp32

    cudaFuncSetAttribute(flash_mma_kernel,
                         cudaFuncAttributeMaxDynamicSharedMemorySize, FLASH_SMEM);

    gemm_tf32_kernel<0><<<dim3(3 * CC / 128, BB * TT / 128), 256>>>(x, W_attn, nullptr);
    flash_mma_kernel<<<dim3(TT / 128, HB_), 256, FLASH_SMEM>>>();
    gemm_tf32_kernel<1><<<dim3(CC / 128, BB * TT / 128), 256>>>(x, W_proj, out);
}

// round 15
// speedup vs baseline: 1.2928x; 1.0843x over previous
#include <cuda_runtime.h>
#include <mma.h>
#include <cstdint>
using namespace nvcuda;

#define BB  4
#define TT  2048
#define CC  1024
#define NH_ 16
#define HS_ 64
#define HB_ (BB * NH_)   // 64 (b,h) pairs

// Scratch (device globals — no allocation allowed)
__device__ float g_q[(size_t)BB * NH_ * TT * HS_];   // [B,NH,t,d], tf32
__device__ float g_k[(size_t)BB * NH_ * TT * HS_];   // [B,NH,t,d], tf32
__device__ float g_v[(size_t)BB * NH_ * TT * HS_];   // [B,NH,d,t] TRANSPOSED, tf32
__device__ float g_y[(size_t)BB * TT * CC];          // [B,T,NH,HS], tf32

__device__ __forceinline__ float ftf(float x) { return wmma::__float_to_tf32(x); }
__device__ __forceinline__ float4 ftf4(float4 v) {
    return make_float4(ftf(v.x), ftf(v.y), ftf(v.z), ftf(v.w));
}
__device__ __forceinline__ float ex2(float x) {
    float r; asm("ex2.approx.ftz.f32 %0, %1;" : "=f"(r) : "f"(x)); return r;
}
__device__ __forceinline__ unsigned su32(const void* p) {
    return (unsigned)__cvta_generic_to_shared(p);
}
#define CPA16(dst, src) \
    asm volatile("cp.async.cg.shared.global [%0], [%1], 16;" :: "r"(dst), "l"(src))
#define CPCOMMIT() asm volatile("cp.async.commit_group;")
template<int N> __device__ __forceinline__ void cpwait() {
    asm volatile("cp.async.wait_group %0;" :: "n"(N));
}

// Raw tf32 MMA m16n8k8 (lane l: g=l>>2, tg=l&3):
//   A: a0=(g,tg) a1=(g+8,tg) a2=(g,tg+4) a3=(g+8,tg+4)
//   B: b0=(k=tg,n=g) b1=(k=tg+4,n=g)
//   C: c0=(g,2tg) c1=(g,2tg+1) c2=(g+8,2tg) c3=(g+8,2tg+1)
__device__ __forceinline__ void mma_tf32(float* d,
    uint32_t a0, uint32_t a1, uint32_t a2, uint32_t a3,
    uint32_t b0, uint32_t b1)
{
    asm volatile("mma.sync.aligned.m16n8k8.row.col.f32.tf32.tf32.f32 "
        "{%0,%1,%2,%3}, {%4,%5,%6,%7}, {%8,%9}, {%0,%1,%2,%3};"
        : "+f"(d[0]), "+f"(d[1]), "+f"(d[2]), "+f"(d[3])
        : "r"(a0), "r"(a1), "r"(a2), "r"(a3), "r"(b0), "r"(b1));
}

__device__ __forceinline__ void ldsm_x4(uint32_t& r0, uint32_t& r1,
                                        uint32_t& r2, uint32_t& r3, uint32_t addr)
{
    asm volatile("ldmatrix.sync.aligned.m8n8.x4.shared.b16 {%0,%1,%2,%3}, [%4];"
        : "=r"(r0), "=r"(r1), "=r"(r2), "=r"(r3) : "r"(addr));
}

// Per-lane ldmatrix row-address offsets (floats, relative to tile origin).
#define AOFF(S) ((((lane & 7) + ((lane >> 3) & 1) * 8) * (S)) + ((lane >> 4) & 1) * 4)
#define BOFF(S) ((((lane & 7) + ((lane >> 4) & 1) * 8) * (S)) + ((lane >> 3) & 1) * 4)

// ---------------------------------------------------------------------------
// TF32 GEMM: C = A @ W^T.  512 threads = 16 warps (4m x 4n), warp tile 32x32,
// 2 CTAs/SM -> 32 warps/SM for latency hiding. Naive LDG + STS (ptxas
// pipelines), tf32 conversion at STS time, static smem.
// EPI==0: scatter q/k ([B,NH,t,d]) and v TRANSPOSED ([B,NH,d,t]), ftf-rounded.
// EPI==1: A := g_y, plain fp32 store.
// ---------------------------------------------------------------------------
template<int EPI>
__global__ __launch_bounds__(512, 2) void gemm_tf32_kernel(
    const float* __restrict__ A, const float* __restrict__ W,
    float* __restrict__ out)
{
    __shared__ __align__(16) float As[128][36];
    __shared__ __align__(16) float Bs[128][36];

    const int tid = threadIdx.x;
    const int bn = blockIdx.x, bm = blockIdx.y;
    const int warp = tid >> 5;
    const int lane = tid & 31;
    const int g = lane >> 2, tg = lane & 3;
    const int wm = warp >> 2, wn = warp & 3;       // 4m x 4n warps
    const int lrow = tid >> 2, lcol = (tid & 3) * 8;

    const int aoff = AOFF(36);
    const int boff = BOFF(36);

    float c[2][4][4];   // warp tile 32x32: 2 m-frags x 4 n-frags
#pragma unroll
    for (int i = 0; i < 2; i++)
#pragma unroll
        for (int j = 0; j < 4; j++)
#pragma unroll
            for (int e = 0; e < 4; e++) c[i][j][e] = 0.0f;

    const float* Asrc = (EPI == 1) ? (const float*)g_y : A;
    const float* Ab = Asrc + (size_t)(bm * 128 + lrow) * CC + lcol;
    const float* Wb = W + (size_t)(bn * 128 + lrow) * CC + lcol;

    const uint32_t asb = su32(&As[0][0]);
    const uint32_t bsb = su32(&Bs[0][0]);

    for (int k0 = 0; k0 < CC; k0 += 32) {
        float4 a[2], b[2];
#pragma unroll
        for (int u = 0; u < 2; u++) {
            a[u] = *(const float4*)(Ab + k0 + u * 4);
            b[u] = *(const float4*)(Wb + k0 + u * 4);
        }
        __syncthreads();
#pragma unroll
        for (int u = 0; u < 2; u++) {
            *(float4*)&As[lrow][lcol + u * 4] = ftf4(a[u]);
            *(float4*)&Bs[lrow][lcol + u * 4] = ftf4(b[u]);
        }
        __syncthreads();
#pragma unroll
        for (int ks = 0; ks < 4; ks++) {
            uint32_t af[2][4], bf[2][4];
#pragma unroll
            for (int i = 0; i < 2; i++)
                ldsm_x4(af[i][0], af[i][1], af[i][2], af[i][3],
                        asb + 4 * ((wm * 32 + i * 16) * 36 + ks * 8 + aoff));
#pragma unroll
            for (int j2 = 0; j2 < 2; j2++)
                ldsm_x4(bf[j2][0], bf[j2][1], bf[j2][2], bf[j2][3],
                        bsb + 4 * ((wn * 32 + j2 * 16) * 36 + ks * 8 + boff));
#pragma unroll
            for (int i = 0; i < 2; i++)
#pragma unroll
                for (int j = 0; j < 4; j++)
                    mma_tf32(c[i][j], af[i][0], af[i][1], af[i][2], af[i][3],
                             bf[j >> 1][(j & 1) * 2], bf[j >> 1][(j & 1) * 2 + 1]);
        }
    }

    // Epilogue: c layout c0=(g,2tg) c1=(g,2tg+1) c2=(g+8,2tg) c3=(g+8,2tg+1)
#pragma unroll
    for (int i = 0; i < 2; i++) {
        int mA = bm * 128 + wm * 32 + i * 16 + g;
        int mB = mA + 8;
#pragma unroll
        for (int j = 0; j < 4; j++) {
            int n = bn * 128 + wn * 32 + j * 8 + 2 * tg;
            if (EPI == 0) {
                int which = n >> 10;
                int cc = n & 1023;
                int head = cc >> 6, d = cc & 63;
                int bA = mA >> 11, tA = mA & 2047;
                int bB = mB >> 11, tB = mB & 2047;
                if (which == 2) {   // v: transposed [B,NH,d,t]
                    float* base = g_v + ((size_t)(bA * NH_ + head) * HS_) * TT;
                    base[(size_t)(d    ) * TT + tA] = ftf(c[i][j][0]);
                    base[(size_t)(d + 1) * TT + tA] = ftf(c[i][j][1]);
                    float* baseB = g_v + ((size_t)(bB * NH_ + head) * HS_) * TT;
                    baseB[(size_t)(d    ) * TT + tB] = ftf(c[i][j][2]);
                    baseB[(size_t)(d + 1) * TT + tB] = ftf(c[i][j][3]);
                } else {
                    float* dst = (which == 0) ? g_q : g_k;
                    *(float2*)&dst[(((size_t)(bA * NH_ + head)) * TT + tA) * HS_ + d] =
                        make_float2(ftf(c[i][j][0]), ftf(c[i][j][1]));
                    *(float2*)&dst[(((size_t)(bB * NH_ + head)) * TT + tB) * HS_ + d] =
                        make_float2(ftf(c[i][j][2]), ftf(c[i][j][3]));
                }
            } else {
                *(float2*)&out[(size_t)mA * CC + n] = make_float2(c[i][j][0], c[i][j][1]);
                *(float2*)&out[(size_t)mB * CC + n] = make_float2(c[i][j][2], c[i][j][3]);
            }
        }
    }
}

// ---------------------------------------------------------------------------
// Flash attention (R10/R12 — frozen): register-resident mma.sync + ldmatrix,
// one barrier per chunk, V^T B-frags.
// ---------------------------------------------------------------------------
#define FLD 68
#define FKV (64 * FLD)
#define FSS (128 * FLD)
#define FLASH_SMEM ((4 * FKV + FSS) * 4)

__global__ __launch_bounds__(256) void flash_mma_kernel()
{
    extern __shared__ __align__(16) float sh[];
    float* Ss = sh + 4 * FKV;

    const int qt = gridDim.x - 1 - blockIdx.x;   // heavy tiles first
    const int hb = blockIdx.y;
    const int tid = threadIdx.x;
    const int warp = tid >> 5;
    const int lane = tid & 31;
    const int g = lane >> 2, tg = lane & 3;
    const int lr = tid >> 2, lq = (tid & 3) * 16;
    const int rq = tid >> 1, hq = tid & 1;

    const int aoff = AOFF(FLD);
    const int boff = BOFF(FLD);
    const int nc = 2 * qt + 2;

    auto issue = [&](int c, int s) {
        const float* kp = g_k + ((size_t)hb * TT + c * 64 + lr) * HS_ + lq;
        const float* vp = g_v + ((size_t)hb * HS_ + lr) * TT + c * 64 + lq;  // [d][t]
        unsigned dk = su32(sh + s * FKV + lr * FLD + lq);
        unsigned dv = su32(sh + (2 + s) * FKV + lr * FLD + lq);
#pragma unroll
        for (int u = 0; u < 4; u++) {
            CPA16(dk + u * 16, kp + u * 4);
            CPA16(dv + u * 16, vp + u * 4);
        }
        CPCOMMIT();
    };

    issue(0, 0);

    // ---- stage Q through own Ss band, pull A-frags via ldmatrix ----
    const float* qp = g_q + ((size_t)hb * TT + qt * 128) * HS_;
    const float qs = 0.125f * 1.44269504f;
#pragma unroll
    for (int u = 0; u < 8; u++) {
        float4 v = *(const float4*)(qp + rq * 64 + hq * 32 + u * 4);
        v.x = ftf(v.x * qs); v.y = ftf(v.y * qs);
        v.z = ftf(v.z * qs); v.w = ftf(v.w * qs);
        *(float4*)&Ss[rq * FLD + hq * 32 + u * 4] = v;
    }
    __syncwarp();
    const uint32_t ssb = su32(Ss);
    uint32_t qa[8][4];
#pragma unroll
    for (int kc = 0; kc < 8; kc++)
        ldsm_x4(qa[kc][0], qa[kc][1], qa[kc][2], qa[kc][3],
                ssb + 4 * ((16 * warp) * FLD + 8 * kc + aoff));
    __syncwarp();

    float o[8][4];
#pragma unroll
    for (int j = 0; j < 8; j++)
#pragma unroll
        for (int e = 0; e < 4; e++) o[j][e] = 0.0f;
    float m0 = -1e30f, m1 = -1e30f, l0 = 0.0f, l1 = 0.0f;

    for (int c = 0; c < nc; c++) {
        cpwait<0>();
        __syncthreads();
        if (c + 1 < nc) issue(c + 1, (c + 1) & 1);

        const uint32_t ksb = su32(sh + (c & 1) * FKV);
        const uint32_t vsb = su32(sh + (2 + (c & 1)) * FKV);

        const int lim = (c >= 2 * qt) ? (16 * warp + 15 - 64 * (c - 2 * qt)) : 127;
        if (lim >= 0) {
            const int j2max = min(3, lim >> 4);
            const int jmax = min(7, 2 * j2max + 1);

            float s[8][4];
#pragma unroll
            for (int j = 0; j < 8; j++)
#pragma unroll
                for (int e = 0; e < 4; e++) s[j][e] = 0.0f;
#pragma unroll
            for (int kc = 0; kc < 8; kc++) {
#pragma unroll
                for (int j2 = 0; j2 < 4; j2++) {
                    if (j2 > j2max) break;
                    uint32_t b0, b1, b2, b3;
                    ldsm_x4(b0, b1, b2, b3,
                            ksb + 4 * ((16 * j2) * FLD + 8 * kc + boff));
                    mma_tf32(s[2 * j2], qa[kc][0], qa[kc][1], qa[kc][2], qa[kc][3], b0, b1);
                    mma_tf32(s[2 * j2 + 1], qa[kc][0], qa[kc][1], qa[kc][2], qa[kc][3], b2, b3);
                }
            }

            if (c >= 2 * qt) {
                const int kb = 64 * (c - 2 * qt);
                const int row0 = 16 * warp + g, row1 = row0 + 8;
#pragma unroll
                for (int j = 0; j < 8; j++) {
                    if (j > jmax) break;
                    int col = kb + 8 * j + 2 * tg;
                    if (col     > row0) s[j][0] = -1e30f;
                    if (col + 1 > row0) s[j][1] = -1e30f;
                    if (col     > row1) s[j][2] = -1e30f;
                    if (col + 1 > row1) s[j][3] = -1e30f;
                }
            }

            float rm0 = -1e30f, rm1 = -1e30f;
#pragma unroll
            for (int j = 0; j < 8; j++) {
                if (j > jmax) break;
                rm0 = fmaxf(rm0, fmaxf(s[j][0], s[j][1]));
                rm1 = fmaxf(rm1, fmaxf(s[j][2], s[j][3]));
            }
            rm0 = fmaxf(rm0, __shfl_xor_sync(0xffffffffu, rm0, 1));
            rm0 = fmaxf(rm0, __shfl_xor_sync(0xffffffffu, rm0, 2));
            rm1 = fmaxf(rm1, __shfl_xor_sync(0xffffffffu, rm1, 1));
            rm1 = fmaxf(rm1, __shfl_xor_sync(0xffffffffu, rm1, 2));
            float mn0 = fmaxf(m0, rm0), mn1 = fmaxf(m1, rm1);
            float corr0 = ex2(m0 - mn0), corr1 = ex2(m1 - mn1);
            float rs0 = 0.0f, rs1 = 0.0f;
#pragma unroll
            for (int j = 0; j < 8; j++) {
                if (j > jmax) break;
                s[j][0] = ex2(s[j][0] - mn0); rs0 += s[j][0];
                s[j][1] = ex2(s[j][1] - mn0); rs0 += s[j][1];
                s[j][2] = ex2(s[j][2] - mn1); rs1 += s[j][2];
                s[j][3] = ex2(s[j][3] - mn1); rs1 += s[j][3];
            }
            rs0 += __shfl_xor_sync(0xffffffffu, rs0, 1);
            rs0 += __shfl_xor_sync(0xffffffffu, rs0, 2);
            rs1 += __shfl_xor_sync(0xffffffffu, rs1, 1);
            rs1 += __shfl_xor_sync(0xffffffffu, rs1, 2);
            l0 = l0 * corr0 + rs0; m0 = mn0;
            l1 = l1 * corr1 + rs1; m1 = mn1;
#pragma unroll
            for (int j = 0; j < 8; j++) {
                o[j][0] *= corr0; o[j][1] *= corr0;
                o[j][2] *= corr1; o[j][3] *= corr1;
            }

            const int pr0 = (16 * warp + g) * FLD, pr1 = (16 * warp + g + 8) * FLD;
#pragma unroll
            for (int j = 0; j < 8; j++) {
                if (j > jmax) break;
                *(float2*)&Ss[pr0 + 8 * j + 2 * tg] =
                    make_float2(ftf(s[j][0]), ftf(s[j][1]));
                *(float2*)&Ss[pr1 + 8 * j + 2 * tg] =
                    make_float2(ftf(s[j][2]), ftf(s[j][3]));
            }
            __syncwarp();

#pragma unroll
            for (int kc = 0; kc < 8; kc++) {
                if (kc > jmax) break;
                uint32_t pa0, pa1, pa2, pa3;
                ldsm_x4(pa0, pa1, pa2, pa3,
                        ssb + 4 * ((16 * warp) * FLD + 8 * kc + aoff));
#pragma unroll
                for (int j2 = 0; j2 < 4; j2++) {
                    uint32_t b0, b1, b2, b3;
                    ldsm_x4(b0, b1, b2, b3,
                            vsb + 4 * ((16 * j2) * FLD + 8 * kc + boff));
                    mma_tf32(o[2 * j2], pa0, pa1, pa2, pa3, b0, b1);
                    mma_tf32(o[2 * j2 + 1], pa0, pa1, pa2, pa3, b2, b3);
                }
            }
            __syncwarp();
        }
    }

    // ---- write O (tf32-rounded, feeds proj) in [B,T,NH,HS] ----
    const float inv0 = 1.0f / l0, inv1 = 1.0f / l1;
    const int b_ = hb >> 4, head = hb & 15;
    const int t0 = qt * 128 + 16 * warp + g, t1 = t0 + 8;
    float* y0 = g_y + (((size_t)(b_ * TT + t0)) * NH_ + head) * HS_;
    float* y1 = g_y + (((size_t)(b_ * TT + t1)) * NH_ + head) * HS_;
#pragma unroll
    for (int j = 0; j < 8; j++) {
        *(float2*)&y0[8 * j + 2 * tg] =
            make_float2(ftf(o[j][0] * inv0), ftf(o[j][1] * inv0));
        *(float2*)&y1[8 * j + 2 * tg] =
            make_float2(ftf(o[j][2] * inv1), ftf(o[j][3] * inv1));
    }
}

// ---------------------------------------------------------------------------
extern "C" void kernel_launch(void* const* d_in, const int* in_sizes, int n_in,
                              void* d_out, int out_size)
{
    const float* x      = (const float*)d_in[0];  // [B,T,C]
    const float* W_attn = (const float*)d_in[1];  // [3C,C]
    const float* W_proj = (const float*)d_in[2];  // [C,C]
    // d_in[3..6] feed a discarded branch — skipped.
    float* out = (float*)d_out;                   // [B,T,C] fp32

    cudaFuncSetAttribute(flash_mma_kernel,
                         cudaFuncAttributeMaxDynamicSharedMemorySize, FLASH_SMEM);

    gemm_tf32_kernel<0><<<dim3(3 * CC / 128, BB * TT / 128), 512>>>(x, W_attn, nullptr);
    flash_mma_kernel<<<dim3(TT / 128, HB_), 256, FLASH_SMEM>>>();
    gemm_tf32_kernel<1><<<dim3(CC / 128, BB * TT / 128), 512>>>(x, W_proj, out);
}

// round 16
// speedup vs baseline: 1.2967x; 1.0030x over previous
#include <cuda_runtime.h>
#include <mma.h>
#include <cstdint>
using namespace nvcuda;

#define BB  4
#define TT  2048
#define CC  1024
#define NH_ 16
#define HS_ 64
#define HB_ (BB * NH_)   // 64 (b,h) pairs

// Scratch (device globals — no allocation allowed)
__device__ float g_q[(size_t)BB * NH_ * TT * HS_];   // [B,NH,t,d], tf32
__device__ float g_k[(size_t)BB * NH_ * TT * HS_];   // [B,NH,t,d], tf32
__device__ float g_v[(size_t)BB * NH_ * TT * HS_];   // [B,NH,d,t] TRANSPOSED, tf32
__device__ float g_y[(size_t)BB * TT * CC];          // [B,T,NH,HS], tf32

__device__ __forceinline__ float ftf(float x) { return wmma::__float_to_tf32(x); }
__device__ __forceinline__ float4 ftf4(float4 v) {
    return make_float4(ftf(v.x), ftf(v.y), ftf(v.z), ftf(v.w));
}
__device__ __forceinline__ float ex2(float x) {
    float r; asm("ex2.approx.ftz.f32 %0, %1;" : "=f"(r) : "f"(x)); return r;
}
__device__ __forceinline__ unsigned su32(const void* p) {
    return (unsigned)__cvta_generic_to_shared(p);
}
#define CPA16(dst, src) \
    asm volatile("cp.async.cg.shared.global [%0], [%1], 16;" :: "r"(dst), "l"(src))
#define CPCOMMIT() asm volatile("cp.async.commit_group;")
template<int N> __device__ __forceinline__ void cpwait() {
    asm volatile("cp.async.wait_group %0;" :: "n"(N));
}

// Raw tf32 MMA m16n8k8 (lane l: g=l>>2, tg=l&3):
//   A: a0=(g,tg) a1=(g+8,tg) a2=(g,tg+4) a3=(g+8,tg+4)
//   B: b0=(k=tg,n=g) b1=(k=tg+4,n=g)
//   C: c0=(g,2tg) c1=(g,2tg+1) c2=(g+8,2tg) c3=(g+8,2tg+1)
__device__ __forceinline__ void mma_tf32(float* d,
    uint32_t a0, uint32_t a1, uint32_t a2, uint32_t a3,
    uint32_t b0, uint32_t b1)
{
    asm volatile("mma.sync.aligned.m16n8k8.row.col.f32.tf32.tf32.f32 "
        "{%0,%1,%2,%3}, {%4,%5,%6,%7}, {%8,%9}, {%0,%1,%2,%3};"
        : "+f"(d[0]), "+f"(d[1]), "+f"(d[2]), "+f"(d[3])
        : "r"(a0), "r"(a1), "r"(a2), "r"(a3), "r"(b0), "r"(b1));
}

__device__ __forceinline__ void ldsm_x4(uint32_t& r0, uint32_t& r1,
                                        uint32_t& r2, uint32_t& r3, uint32_t addr)
{
    asm volatile("ldmatrix.sync.aligned.m8n8.x4.shared.b16 {%0,%1,%2,%3}, [%4];"
        : "=r"(r0), "=r"(r1), "=r"(r2), "=r"(r3) : "r"(addr));
}

// Per-lane ldmatrix row-address offsets (floats, relative to tile origin).
#define AOFF(S) ((((lane & 7) + ((lane >> 3) & 1) * 8) * (S)) + ((lane >> 4) & 1) * 4)
#define BOFF(S) ((((lane & 7) + ((lane >> 4) & 1) * 8) * (S)) + ((lane >> 3) & 1) * 4)

// ---------------------------------------------------------------------------
// TF32 GEMM (R15 — at tf32 issue roof, FROZEN): C = A @ W^T.
// 512 threads = 16 warps (4m x 4n), warp tile 32x32, 2 CTAs/SM.
// ---------------------------------------------------------------------------
template<int EPI>
__global__ __launch_bounds__(512, 2) void gemm_tf32_kernel(
    const float* __restrict__ A, const float* __restrict__ W,
    float* __restrict__ out)
{
    __shared__ __align__(16) float As[128][36];
    __shared__ __align__(16) float Bs[128][36];

    const int tid = threadIdx.x;
    const int bn = blockIdx.x, bm = blockIdx.y;
    const int warp = tid >> 5;
    const int lane = tid & 31;
    const int g = lane >> 2, tg = lane & 3;
    const int wm = warp >> 2, wn = warp & 3;       // 4m x 4n warps
    const int lrow = tid >> 2, lcol = (tid & 3) * 8;

    const int aoff = AOFF(36);
    const int boff = BOFF(36);

    float c[2][4][4];
#pragma unroll
    for (int i = 0; i < 2; i++)
#pragma unroll
        for (int j = 0; j < 4; j++)
#pragma unroll
            for (int e = 0; e < 4; e++) c[i][j][e] = 0.0f;

    const float* Asrc = (EPI == 1) ? (const float*)g_y : A;
    const float* Ab = Asrc + (size_t)(bm * 128 + lrow) * CC + lcol;
    const float* Wb = W + (size_t)(bn * 128 + lrow) * CC + lcol;

    const uint32_t asb = su32(&As[0][0]);
    const uint32_t bsb = su32(&Bs[0][0]);

    for (int k0 = 0; k0 < CC; k0 += 32) {
        float4 a[2], b[2];
#pragma unroll
        for (int u = 0; u < 2; u++) {
            a[u] = *(const float4*)(Ab + k0 + u * 4);
            b[u] = *(const float4*)(Wb + k0 + u * 4);
        }
        __syncthreads();
#pragma unroll
        for (int u = 0; u < 2; u++) {
            *(float4*)&As[lrow][lcol + u * 4] = ftf4(a[u]);
            *(float4*)&Bs[lrow][lcol + u * 4] = ftf4(b[u]);
        }
        __syncthreads();
#pragma unroll
        for (int ks = 0; ks < 4; ks++) {
            uint32_t af[2][4], bf[2][4];
#pragma unroll
            for (int i = 0; i < 2; i++)
                ldsm_x4(af[i][0], af[i][1], af[i][2], af[i][3],
                        asb + 4 * ((wm * 32 + i * 16) * 36 + ks * 8 + aoff));
#pragma unroll
            for (int j2 = 0; j2 < 2; j2++)
                ldsm_x4(bf[j2][0], bf[j2][1], bf[j2][2], bf[j2][3],
                        bsb + 4 * ((wn * 32 + j2 * 16) * 36 + ks * 8 + boff));
#pragma unroll
            for (int i = 0; i < 2; i++)
#pragma unroll
                for (int j = 0; j < 4; j++)
                    mma_tf32(c[i][j], af[i][0], af[i][1], af[i][2], af[i][3],
                             bf[j >> 1][(j & 1) * 2], bf[j >> 1][(j & 1) * 2 + 1]);
        }
    }

#pragma unroll
    for (int i = 0; i < 2; i++) {
        int mA = bm * 128 + wm * 32 + i * 16 + g;
        int mB = mA + 8;
#pragma unroll
        for (int j = 0; j < 4; j++) {
            int n = bn * 128 + wn * 32 + j * 8 + 2 * tg;
            if (EPI == 0) {
                int which = n >> 10;
                int cc = n & 1023;
                int head = cc >> 6, d = cc & 63;
                int bA = mA >> 11, tA = mA & 2047;
                int bB = mB >> 11, tB = mB & 2047;
                if (which == 2) {   // v: transposed [B,NH,d,t]
                    float* base = g_v + ((size_t)(bA * NH_ + head) * HS_) * TT;
                    base[(size_t)(d    ) * TT + tA] = ftf(c[i][j][0]);
                    base[(size_t)(d + 1) * TT + tA] = ftf(c[i][j][1]);
                    float* baseB = g_v + ((size_t)(bB * NH_ + head) * HS_) * TT;
                    baseB[(size_t)(d    ) * TT + tB] = ftf(c[i][j][2]);
                    baseB[(size_t)(d + 1) * TT + tB] = ftf(c[i][j][3]);
                } else {
                    float* dst = (which == 0) ? g_q : g_k;
                    *(float2*)&dst[(((size_t)(bA * NH_ + head)) * TT + tA) * HS_ + d] =
                        make_float2(ftf(c[i][j][0]), ftf(c[i][j][1]));
                    *(float2*)&dst[(((size_t)(bB * NH_ + head)) * TT + tB) * HS_ + d] =
                        make_float2(ftf(c[i][j][2]), ftf(c[i][j][3]));
                }
            } else {
                *(float2*)&out[(size_t)mA * CC + n] = make_float2(c[i][j][0], c[i][j][1]);
                *(float2*)&out[(size_t)mB * CC + n] = make_float2(c[i][j][2], c[i][j][3]);
            }
        }
    }
}

// ---------------------------------------------------------------------------
// Flash attention: chunk processed as two 32-key halves (s[4][4] live) to cut
// registers; __launch_bounds__(256,2) pins 2 CTAs/SM (16 warps) so one CTA's
// softmax/MUFU phase overlaps the other's tensor phase.
// ---------------------------------------------------------------------------
#define FLD 68
#define FKV (64 * FLD)
#define FSS (128 * FLD)
#define FLASH_SMEM ((4 * FKV + FSS) * 4)

__global__ __launch_bounds__(256, 2) void flash_mma_kernel()
{
    extern __shared__ __align__(16) float sh[];
    float* Ss = sh + 4 * FKV;

    const int qt = gridDim.x - 1 - blockIdx.x;   // heavy tiles first
    const int hb = blockIdx.y;
    const int tid = threadIdx.x;
    const int warp = tid >> 5;
    const int lane = tid & 31;
    const int g = lane >> 2, tg = lane & 3;
    const int lr = tid >> 2, lq = (tid & 3) * 16;
    const int rq = tid >> 1, hq = tid & 1;

    const int aoff = AOFF(FLD);
    const int boff = BOFF(FLD);
    const int nc = 2 * qt + 2;

    auto issue = [&](int c, int s) {
        const float* kp = g_k + ((size_t)hb * TT + c * 64 + lr) * HS_ + lq;
        const float* vp = g_v + ((size_t)hb * HS_ + lr) * TT + c * 64 + lq;  // [d][t]
        unsigned dk = su32(sh + s * FKV + lr * FLD + lq);
        unsigned dv = su32(sh + (2 + s) * FKV + lr * FLD + lq);
#pragma unroll
        for (int u = 0; u < 4; u++) {
            CPA16(dk + u * 16, kp + u * 4);
            CPA16(dv + u * 16, vp + u * 4);
        }
        CPCOMMIT();
    };

    issue(0, 0);

    // ---- stage Q through own Ss band, pull A-frags via ldmatrix ----
    const float* qp = g_q + ((size_t)hb * TT + qt * 128) * HS_;
    const float qs = 0.125f * 1.44269504f;
#pragma unroll
    for (int u = 0; u < 8; u++) {
        float4 v = *(const float4*)(qp + rq * 64 + hq * 32 + u * 4);
        v.x = ftf(v.x * qs); v.y = ftf(v.y * qs);
        v.z = ftf(v.z * qs); v.w = ftf(v.w * qs);
        *(float4*)&Ss[rq * FLD + hq * 32 + u * 4] = v;
    }
    __syncwarp();
    const uint32_t ssb = su32(Ss);
    uint32_t qa[8][4];
#pragma unroll
    for (int kc = 0; kc < 8; kc++)
        ldsm_x4(qa[kc][0], qa[kc][1], qa[kc][2], qa[kc][3],
                ssb + 4 * ((16 * warp) * FLD + 8 * kc + aoff));
    __syncwarp();

    float o[8][4];
#pragma unroll
    for (int j = 0; j < 8; j++)
#pragma unroll
        for (int e = 0; e < 4; e++) o[j][e] = 0.0f;
    float m0 = -1e30f, m1 = -1e30f, l0 = 0.0f, l1 = 0.0f;

    const int pr0 = (16 * warp + g) * FLD, pr1 = (16 * warp + g + 8) * FLD;

    for (int c = 0; c < nc; c++) {
        cpwait<0>();
        __syncthreads();
        if (c + 1 < nc) issue(c + 1, (c + 1) & 1);

        const uint32_t ksb = su32(sh + (c & 1) * FKV);
        const uint32_t vsb = su32(sh + (2 + (c & 1)) * FKV);

        // lim = max allowed key index (0..63 within chunk), 127 = unmasked
        const int lim = (c >= 2 * qt) ? (16 * warp + 15 - 64 * (c - 2 * qt)) : 127;

#pragma unroll
        for (int h2 = 0; h2 < 2; h2++) {
            const int bk = 32 * h2;              // half base key
            if (lim < bk) break;
            const int hlim = min(31, lim - bk);  // max key within half
            const int j2max = hlim >> 4;         // 16-key tiles: 0..1
            const int jmax = hlim >> 3;          // 8-key groups: 0..3

            // ---- S_half = Q K^T ----
            float s[4][4];
#pragma unroll
            for (int j = 0; j < 4; j++)
#pragma unroll
                for (int e = 0; e < 4; e++) s[j][e] = 0.0f;
#pragma unroll
            for (int kc = 0; kc < 8; kc++) {
#pragma unroll
                for (int j2 = 0; j2 < 2; j2++) {
                    if (j2 > j2max) break;
                    uint32_t b0, b1, b2, b3;
                    ldsm_x4(b0, b1, b2, b3,
                            ksb + 4 * ((bk + 16 * j2) * FLD + 8 * kc + boff));
                    mma_tf32(s[2 * j2], qa[kc][0], qa[kc][1], qa[kc][2], qa[kc][3], b0, b1);
                    mma_tf32(s[2 * j2 + 1], qa[kc][0], qa[kc][1], qa[kc][2], qa[kc][3], b2, b3);
                }
            }

            // ---- causal mask ----
            if (c >= 2 * qt) {
                const int kb = 64 * (c - 2 * qt) + bk;
                const int row0 = 16 * warp + g, row1 = row0 + 8;
#pragma unroll
                for (int j = 0; j < 4; j++) {
                    if (j > jmax) break;
                    int col = kb + 8 * j + 2 * tg;
                    if (col     > row0) s[j][0] = -1e30f;
                    if (col + 1 > row0) s[j][1] = -1e30f;
                    if (col     > row1) s[j][2] = -1e30f;
                    if (col + 1 > row1) s[j][3] = -1e30f;
                }
            }

            // ---- online softmax merge (rows g, g+8) ----
            float rm0 = -1e30f, rm1 = -1e30f;
#pragma unroll
            for (int j = 0; j < 4; j++) {
                if (j > jmax) break;
                rm0 = fmaxf(rm0, fmaxf(s[j][0], s[j][1]));
                rm1 = fmaxf(rm1, fmaxf(s[j][2], s[j][3]));
            }
            rm0 = fmaxf(rm0, __shfl_xor_sync(0xffffffffu, rm0, 1));
            rm0 = fmaxf(rm0, __shfl_xor_sync(0xffffffffu, rm0, 2));
            rm1 = fmaxf(rm1, __shfl_xor_sync(0xffffffffu, rm1, 1));
            rm1 = fmaxf(rm1, __shfl_xor_sync(0xffffffffu, rm1, 2));
            float mn0 = fmaxf(m0, rm0), mn1 = fmaxf(m1, rm1);
            float corr0 = ex2(m0 - mn0), corr1 = ex2(m1 - mn1);
            float rs0 = 0.0f, rs1 = 0.0f;
#pragma unroll
            for (int j = 0; j < 4; j++) {
                if (j > jmax) break;
                s[j][0] = ex2(s[j][0] - mn0); rs0 += s[j][0];
                s[j][1] = ex2(s[j][1] - mn0); rs0 += s[j][1];
                s[j][2] = ex2(s[j][2] - mn1); rs1 += s[j][2];
                s[j][3] = ex2(s[j][3] - mn1); rs1 += s[j][3];
            }
            rs0 += __shfl_xor_sync(0xffffffffu, rs0, 1);
            rs0 += __shfl_xor_sync(0xffffffffu, rs0, 2);
            rs1 += __shfl_xor_sync(0xffffffffu, rs1, 1);
            rs1 += __shfl_xor_sync(0xffffffffu, rs1, 2);
            l0 = l0 * corr0 + rs0; m0 = mn0;
            l1 = l1 * corr1 + rs1; m1 = mn1;
#pragma unroll
            for (int j = 0; j < 8; j++) {
                o[j][0] *= corr0; o[j][1] *= corr0;
                o[j][2] *= corr1; o[j][3] *= corr1;
            }

            // ---- P half to warp-private band (tf32) ----
#pragma unroll
            for (int j = 0; j < 4; j++) {
                if (j > jmax) break;
                *(float2*)&Ss[pr0 + bk + 8 * j + 2 * tg] =
                    make_float2(ftf(s[j][0]), ftf(s[j][1]));
                *(float2*)&Ss[pr1 + bk + 8 * j + 2 * tg] =
                    make_float2(ftf(s[j][2]), ftf(s[j][3]));
            }
            __syncwarp();

            // ---- O += P_half @ V_half (V^T tiles) ----
#pragma unroll
            for (int jj = 0; jj < 4; jj++) {
                if (jj > jmax) break;
                uint32_t pa0, pa1, pa2, pa3;
                ldsm_x4(pa0, pa1, pa2, pa3,
                        ssb + 4 * ((16 * warp) * FLD + bk + 8 * jj + aoff));
#pragma unroll
                for (int j2 = 0; j2 < 4; j2++) {
                    uint32_t b0, b1, b2, b3;
                    ldsm_x4(b0, b1, b2, b3,
                            vsb + 4 * ((16 * j2) * FLD + bk + 8 * jj + boff));
                    mma_tf32(o[2 * j2], pa0, pa1, pa2, pa3, b0, b1);
                    mma_tf32(o[2 * j2 + 1], pa0, pa1, pa2, pa3, b2, b3);
                }
            }
            __syncwarp();
        }
    }

    // ---- write O (tf32-rounded, feeds proj) in [B,T,NH,HS] ----
    const float inv0 = 1.0f / l0, inv1 = 1.0f / l1;
    const int b_ = hb >> 4, head = hb & 15;
    const int t0 = qt * 128 + 16 * warp + g, t1 = t0 + 8;
    float* y0 = g_y + (((size_t)(b_ * TT + t0)) * NH_ + head) * HS_;
    float* y1 = g_y + (((size_t)(b_ * TT + t1)) * NH_ + head) * HS_;
#pragma unroll
    for (int j = 0; j < 8; j++) {
        *(float2*)&y0[8 * j + 2 * tg] =
            make_float2(ftf(o[j][0] * inv0), ftf(o[j][1] * inv0));
        *(float2*)&y1[8 * j + 2 * tg] =
            make_float2(ftf(o[j][2] * inv1), ftf(o[j][3] * inv1));
    }
}

// ---------------------------------------------------------------------------
extern "C" void kernel_launch(void* const* d_in, const int* in_sizes, int n_in,
                              void* d_out, int out_size)
{
    const float* x      = (const float*)d_in[0];  // [B,T,C]
    const float* W_attn = (const float*)d_in[1];  // [3C,C]
    const float* W_proj = (const float*)d_in[2];  // [C,C]
    // d_in[3..6] feed a discarded branch — skipped.
    float* out = (float*)d_out;                   // [B,T,C] fp32

    cudaFuncSetAttribute(flash_mma_kernel,
                         cudaFuncAttributeMaxDynamicSharedMemorySize, FLASH_SMEM);

    gemm_tf32_kernel<0><<<dim3(3 * CC / 128, BB * TT / 128), 512>>>(x, W_attn, nullptr);
    flash_mma_kernel<<<dim3(TT / 128, HB_), 256, FLASH_SMEM>>>();
    gemm_tf32_kernel<1><<<dim3(CC / 128, BB * TT / 128), 512>>>(x, W_proj, out);
}

// round 17
// speedup vs baseline: 2.0551x; 1.5848x over previous
#include <cuda_runtime.h>
#include <cuda_fp16.h>
#include <cstdint>

#define BB  4
#define TT  2048
#define CC  1024
#define NH_ 16
#define HS_ 64
#define HB_ (BB * NH_)   // 64 (b,h) pairs

// Scratch (device globals — no allocation allowed)
__device__ __half g_q[(size_t)BB * NH_ * TT * HS_];  // [B,NH,t,d]
__device__ __half g_k[(size_t)BB * NH_ * TT * HS_];  // [B,NH,t,d]
__device__ __half g_v[(size_t)BB * NH_ * TT * HS_];  // [B,NH,d,t] TRANSPOSED
__device__ __half g_y[(size_t)BB * TT * CC];         // [B,T,NH,HS]

__device__ __forceinline__ float ex2(float x) {
    float r; asm("ex2.approx.ftz.f32 %0, %1;" : "=f"(r) : "f"(x)); return r;
}
__device__ __forceinline__ unsigned su32(const void* p) {
    return (unsigned)__cvta_generic_to_shared(p);
}
__device__ __forceinline__ uint32_t ph2(float a, float b) {
    __half2 h = __floats2half2_rn(a, b);
    return *(uint32_t*)&h;
}
#define CPA16(dst, src) \
    asm volatile("cp.async.cg.shared.global [%0], [%1], 16;" :: "r"(dst), "l"(src))
#define CPCOMMIT() asm volatile("cp.async.commit_group;")
template<int N> __device__ __forceinline__ void cpwait() {
    asm volatile("cp.async.wait_group %0;" :: "n"(N));
}

// fp16 MMA m16n8k16, fp32 accum (lane l: g=l>>2, tg=l&3):
//   A regs a0..a3 = quadrants (m0-7,k0-7)(m8-15,k0-7)(m0-7,k8-15)(m8-15,k8-15)
//   B regs b0,b1  = (n0-7,k0-7),(n0-7,k8-15)
//   C: c0=(g,2tg) c1=(g,2tg+1) c2=(g+8,2tg) c3=(g+8,2tg+1)
__device__ __forceinline__ void mma_f16(float* d,
    uint32_t a0, uint32_t a1, uint32_t a2, uint32_t a3,
    uint32_t b0, uint32_t b1)
{
    asm volatile("mma.sync.aligned.m16n8k16.row.col.f32.f16.f16.f32 "
        "{%0,%1,%2,%3}, {%4,%5,%6,%7}, {%8,%9}, {%0,%1,%2,%3};"
        : "+f"(d[0]), "+f"(d[1]), "+f"(d[2]), "+f"(d[3])
        : "r"(a0), "r"(a1), "r"(a2), "r"(a3), "r"(b0), "r"(b1));
}

__device__ __forceinline__ void ldsm_x4(uint32_t& r0, uint32_t& r1,
                                        uint32_t& r2, uint32_t& r3, uint32_t addr)
{
    asm volatile("ldmatrix.sync.aligned.m8n8.x4.shared.b16 {%0,%1,%2,%3}, [%4];"
        : "=r"(r0), "=r"(r1), "=r"(r2), "=r"(r3) : "r"(addr));
}

// Per-lane ldmatrix row offsets (HALF units, relative to tile origin), stride S halves.
// A tile [16 m][16 k]: quadrants (m0-7,k0-7)(m8-15,k0-7)(m0-7,k8-15)(m8-15,k8-15)
#define AOFFH(S) (((lane & 15) * (S)) + ((lane >> 4) & 1) * 8)
// B tile [16 n][16 k]: quadrants (n0-7,k0-7)(n0-7,k8-15)(n8-15,k0-7)(n8-15,k8-15)
//  -> regs r0,r1 serve n-tile 0 (b0,b1); r2,r3 serve n-tile 1.
#define BOFFH(S) ((((lane & 7) + ((lane >> 4) & 1) * 8) * (S)) + ((lane >> 3) & 1) * 8)

// ---------------------------------------------------------------------------
// FP16 GEMM: C = A @ W^T. 512 threads = 16 warps (4m x 4n), warp tile 32x32,
// BK=32 (2 k16 steps), 2 CTAs/SM. fp32->fp16 at STS (EPI==0: A,W fp32;
// EPI==1: A := g_y half, W fp32). fp32 accumulate.
// EPI==0: scatter q/k half ([B,NH,t,d]) and v TRANSPOSED half ([B,NH,d,t]).
// EPI==1: plain fp32 store.
// ---------------------------------------------------------------------------
#define GLDH 40   // half stride (80B rows, conflict-free ldmatrix)

template<int EPI>
__global__ __launch_bounds__(512, 2) void gemm_f16_kernel(
    const float* __restrict__ A, const float* __restrict__ W,
    float* __restrict__ out)
{
    __shared__ __align__(16) __half As[128][GLDH];
    __shared__ __align__(16) __half Bs[128][GLDH];

    const int tid = threadIdx.x;
    const int bn = blockIdx.x, bm = blockIdx.y;
    const int warp = tid >> 5;
    const int lane = tid & 31;
    const int g = lane >> 2, tg = lane & 3;
    const int wm = warp >> 2, wn = warp & 3;       // 4m x 4n warps
    const int lrow = tid >> 2, lcol = (tid & 3) * 8;

    const int aoff = AOFFH(GLDH);
    const int boff = BOFFH(GLDH);

    float c[2][4][4];
#pragma unroll
    for (int i = 0; i < 2; i++)
#pragma unroll
        for (int j = 0; j < 4; j++)
#pragma unroll
            for (int e = 0; e < 4; e++) c[i][j][e] = 0.0f;

    const float* Ab = A + (size_t)(bm * 128 + lrow) * CC + lcol;          // EPI==0
    const __half* Ah = (const __half*)g_y + (size_t)(bm * 128 + lrow) * CC + lcol; // EPI==1
    const float* Wb = W + (size_t)(bn * 128 + lrow) * CC + lcol;

    const uint32_t asb = su32(&As[0][0]);
    const uint32_t bsb = su32(&Bs[0][0]);

    for (int k0 = 0; k0 < CC; k0 += 32) {
        uint4 av, bv;
        if (EPI == 0) {
            float4 a0 = *(const float4*)(Ab + k0);
            float4 a1 = *(const float4*)(Ab + k0 + 4);
            av.x = ph2(a0.x, a0.y); av.y = ph2(a0.z, a0.w);
            av.z = ph2(a1.x, a1.y); av.w = ph2(a1.z, a1.w);
        } else {
            av = *(const uint4*)(Ah + k0);
        }
        {
            float4 b0 = *(const float4*)(Wb + k0);
            float4 b1 = *(const float4*)(Wb + k0 + 4);
            bv.x = ph2(b0.x, b0.y); bv.y = ph2(b0.z, b0.w);
            bv.z = ph2(b1.x, b1.y); bv.w = ph2(b1.z, b1.w);
        }
        __syncthreads();
        *(uint4*)&As[lrow][lcol] = av;
        *(uint4*)&Bs[lrow][lcol] = bv;
        __syncthreads();
#pragma unroll
        for (int ks = 0; ks < 2; ks++) {
            uint32_t af[2][4], bf[2][4];
#pragma unroll
            for (int i = 0; i < 2; i++)
                ldsm_x4(af[i][0], af[i][1], af[i][2], af[i][3],
                        asb + 2 * ((wm * 32 + i * 16) * GLDH + ks * 16 + aoff));
#pragma unroll
            for (int j2 = 0; j2 < 2; j2++)
                ldsm_x4(bf[j2][0], bf[j2][1], bf[j2][2], bf[j2][3],
                        bsb + 2 * ((wn * 32 + j2 * 16) * GLDH + ks * 16 + boff));
#pragma unroll
            for (int i = 0; i < 2; i++)
#pragma unroll
                for (int j = 0; j < 4; j++)
                    mma_f16(c[i][j], af[i][0], af[i][1], af[i][2], af[i][3],
                            bf[j >> 1][(j & 1) * 2], bf[j >> 1][(j & 1) * 2 + 1]);
        }
    }

    // Epilogue: c0=(g,2tg) c1=(g,2tg+1) c2=(g+8,2tg) c3=(g+8,2tg+1)
#pragma unroll
    for (int i = 0; i < 2; i++) {
        int mA = bm * 128 + wm * 32 + i * 16 + g;
        int mB = mA + 8;
#pragma unroll
        for (int j = 0; j < 4; j++) {
            int n = bn * 128 + wn * 32 + j * 8 + 2 * tg;
            if (EPI == 0) {
                int which = n >> 10;
                int cc = n & 1023;
                int head = cc >> 6, d = cc & 63;
                int bA = mA >> 11, tA = mA & 2047;
                int bB = mB >> 11, tB = mB & 2047;
                if (which == 2) {   // v: transposed [B,NH,d,t]
                    __half* base = g_v + ((size_t)(bA * NH_ + head) * HS_) * TT;
                    base[(size_t)(d    ) * TT + tA] = __float2half_rn(c[i][j][0]);
                    base[(size_t)(d + 1) * TT + tA] = __float2half_rn(c[i][j][1]);
                    __half* baseB = g_v + ((size_t)(bB * NH_ + head) * HS_) * TT;
                    baseB[(size_t)(d    ) * TT + tB] = __float2half_rn(c[i][j][2]);
                    baseB[(size_t)(d + 1) * TT + tB] = __float2half_rn(c[i][j][3]);
                } else {
                    __half* dst = (which == 0) ? g_q : g_k;
                    *(uint32_t*)&dst[(((size_t)(bA * NH_ + head)) * TT + tA) * HS_ + d] =
                        ph2(c[i][j][0], c[i][j][1]);
                    *(uint32_t*)&dst[(((size_t)(bB * NH_ + head)) * TT + tB) * HS_ + d] =
                        ph2(c[i][j][2], c[i][j][3]);
                }
            } else {
                *(float2*)&out[(size_t)mA * CC + n] = make_float2(c[i][j][0], c[i][j][1]);
                *(float2*)&out[(size_t)mB * CC + n] = make_float2(c[i][j][2], c[i][j][3]);
            }
        }
    }
}

// ---------------------------------------------------------------------------
// Flash attention, fp16 m16n8k16. Structure from R15/16: 256 threads = 8 warps,
// warp owns 16 q-rows; K/V cp.async double-buffered; 32-key halves; register
// S/O; P staged as half2 in warp-private band. smem 54KB -> 2 CTAs/SM.
// ---------------------------------------------------------------------------
#define FLDH 72                 // half stride (144B rows)
#define FKVH (64 * FLDH)        // one K or V tile (halves)
#define FSSH (128 * FLDH)       // Q/P staging (halves)
#define FLASH_SMEM ((4 * FKVH + FSSH) * 2)   // 55296 B

__global__ __launch_bounds__(256, 2) void flash_f16_kernel()
{
    extern __shared__ __align__(16) __half shh[];
    __half* Ss = shh + 4 * FKVH;

    const int qt = gridDim.x - 1 - blockIdx.x;   // heavy tiles first
    const int hb = blockIdx.y;
    const int tid = threadIdx.x;
    const int warp = tid >> 5;
    const int lane = tid & 31;
    const int g = lane >> 2, tg = lane & 3;
    const int lr = tid >> 2, lq = (tid & 3) * 16;   // K/V loader: 4 thr/row, 16 halves each
    const int rq = tid >> 1, hq = (tid & 1) * 32;   // Q loader: 2 thr/row, 32 halves each

    const int aoff = AOFFH(FLDH);
    const int boff = BOFFH(FLDH);
    const int nc = 2 * qt + 2;

    auto issue = [&](int c, int s) {
        const __half* kp = g_k + ((size_t)hb * TT + c * 64 + lr) * HS_ + lq;
        const __half* vp = g_v + ((size_t)hb * HS_ + lr) * TT + c * 64 + lq;  // [d][t]
        unsigned dk = su32(shh + s * FKVH + lr * FLDH + lq);
        unsigned dv = su32(shh + (2 + s) * FKVH + lr * FLDH + lq);
#pragma unroll
        for (int u = 0; u < 2; u++) {
            CPA16(dk + u * 16, kp + u * 8);
            CPA16(dv + u * 16, vp + u * 8);
        }
        CPCOMMIT();
    };

    issue(0, 0);

    // ---- stage Q (scaled) into own Ss band, pull A-frags via ldmatrix ----
    const __half* qp = g_q + ((size_t)hb * TT + qt * 128) * HS_;
    const float qs = 0.125f * 1.44269504f;
#pragma unroll
    for (int u = 0; u < 4; u++) {
        uint4 v = *(const uint4*)(qp + rq * 64 + hq + u * 8);
        uint32_t* w = (uint32_t*)&v;
#pragma unroll
        for (int e = 0; e < 4; e++) {
            float2 f = __half22float2(*(__half2*)&w[e]);
            w[e] = ph2(f.x * qs, f.y * qs);
        }
        *(uint4*)&Ss[rq * FLDH + hq + u * 8] = v;
    }
    __syncwarp();
    const uint32_t ssb = su32(Ss);
    uint32_t qa[4][4];
#pragma unroll
    for (int kc = 0; kc < 4; kc++)
        ldsm_x4(qa[kc][0], qa[kc][1], qa[kc][2], qa[kc][3],
                ssb + 2 * ((16 * warp) * FLDH + kc * 16 + aoff));
    __syncwarp();

    float o[8][4];
#pragma unroll
    for (int j = 0; j < 8; j++)
#pragma unroll
        for (int e = 0; e < 4; e++) o[j][e] = 0.0f;
    float m0 = -1e30f, m1 = -1e30f, l0 = 0.0f, l1 = 0.0f;

    const int pr0 = (16 * warp + g) * FLDH, pr1 = (16 * warp + g + 8) * FLDH;

    for (int c = 0; c < nc; c++) {
        cpwait<0>();
        __syncthreads();
        if (c + 1 < nc) issue(c + 1, (c + 1) & 1);

        const uint32_t ksb = su32(shh + (c & 1) * FKVH);
        const uint32_t vsb = su32(shh + (2 + (c & 1)) * FKVH);

        // lim = max allowed key index within chunk (0..63); 127 = unmasked
        const int lim = (c >= 2 * qt) ? (16 * warp + 15 - 64 * (c - 2 * qt)) : 127;

#pragma unroll
        for (int h2 = 0; h2 < 2; h2++) {
            const int bk = 32 * h2;
            if (lim < bk) break;
            const int hlim = min(31, lim - bk);
            const int j2max = hlim >> 4;   // 16-key S tiles / PV k16 steps
            const int jmax = hlim >> 3;    // 8-key groups

            // ---- S_half = Q K^T (k = d, 4 k16 steps) ----
            float s[4][4];
#pragma unroll
            for (int j = 0; j < 4; j++)
#pragma unroll
                for (int e = 0; e < 4; e++) s[j][e] = 0.0f;
#pragma unroll
            for (int kc = 0; kc < 4; kc++) {
#pragma unroll
                for (int j2 = 0; j2 < 2; j2++) {
                    if (j2 > j2max) break;
                    uint32_t b0, b1, b2, b3;
                    ldsm_x4(b0, b1, b2, b3,
                            ksb + 2 * ((bk + 16 * j2) * FLDH + kc * 16 + boff));
                    mma_f16(s[2 * j2], qa[kc][0], qa[kc][1], qa[kc][2], qa[kc][3], b0, b1);
                    mma_f16(s[2 * j2 + 1], qa[kc][0], qa[kc][1], qa[kc][2], qa[kc][3], b2, b3);
                }
            }

            // ---- causal mask ----
            if (c >= 2 * qt) {
                const int kb = 64 * (c - 2 * qt) + bk;
                const int row0 = 16 * warp + g, row1 = row0 + 8;
#pragma unroll
                for (int j = 0; j < 4; j++) {
                    if (j > jmax) break;
                    int col = kb + 8 * j + 2 * tg;
                    if (col     > row0) s[j][0] = -1e30f;
                    if (col + 1 > row0) s[j][1] = -1e30f;
                    if (col     > row1) s[j][2] = -1e30f;
                    if (col + 1 > row1) s[j][3] = -1e30f;
                }
            }

            // ---- online softmax merge (rows g, g+8) ----
            float rm0 = -1e30f, rm1 = -1e30f;
#pragma unroll
            for (int j = 0; j < 4; j++) {
                if (j > jmax) break;
                rm0 = fmaxf(rm0, fmaxf(s[j][0], s[j][1]));
                rm1 = fmaxf(rm1, fmaxf(s[j][2], s[j][3]));
            }
            rm0 = fmaxf(rm0, __shfl_xor_sync(0xffffffffu, rm0, 1));
            rm0 = fmaxf(rm0, __shfl_xor_sync(0xffffffffu, rm0, 2));
            rm1 = fmaxf(rm1, __shfl_xor_sync(0xffffffffu, rm1, 1));
            rm1 = fmaxf(rm1, __shfl_xor_sync(0xffffffffu, rm1, 2));
            float mn0 = fmaxf(m0, rm0), mn1 = fmaxf(m1, rm1);
            float corr0 = ex2(m0 - mn0), corr1 = ex2(m1 - mn1);
            float rs0 = 0.0f, rs1 = 0.0f;
#pragma unroll
            for (int j = 0; j < 4; j++) {
                if (j > jmax) break;
                s[j][0] = ex2(s[j][0] - mn0); rs0 += s[j][0];
                s[j][1] = ex2(s[j][1] - mn0); rs0 += s[j][1];
                s[j][2] = ex2(s[j][2] - mn1); rs1 += s[j][2];
                s[j][3] = ex2(s[j][3] - mn1); rs1 += s[j][3];
            }
            rs0 += __shfl_xor_sync(0xffffffffu, rs0, 1);
            rs0 += __shfl_xor_sync(0xffffffffu, rs0, 2);
            rs1 += __shfl_xor_sync(0xffffffffu, rs1, 1);
            rs1 += __shfl_xor_sync(0xffffffffu, rs1, 2);
            l0 = l0 * corr0 + rs0; m0 = mn0;
            l1 = l1 * corr1 + rs1; m1 = mn1;
#pragma unroll
            for (int j = 0; j < 8; j++) {
                o[j][0] *= corr0; o[j][1] *= corr0;
                o[j][2] *= corr1; o[j][3] *= corr1;
            }

            // ---- P half to warp-private band (ALL 4 groups; skipped = 0) ----
#pragma unroll
            for (int j = 0; j < 4; j++) {
                *(uint32_t*)&Ss[pr0 + bk + 8 * j + 2 * tg] = ph2(s[j][0], s[j][1]);
                *(uint32_t*)&Ss[pr1 + bk + 8 * j + 2 * tg] = ph2(s[j][2], s[j][3]);
            }
            __syncwarp();

            // ---- O += P_half @ V_half (k = keys, 2 k16 steps; V^T tiles) ----
#pragma unroll
            for (int kk = 0; kk < 2; kk++) {
                if (kk > j2max) break;
                uint32_t pa0, pa1, pa2, pa3;
                ldsm_x4(pa0, pa1, pa2, pa3,
                        ssb + 2 * ((16 * warp) * FLDH + bk + 16 * kk + aoff));
#pragma unroll
                for (int j2 = 0; j2 < 4; j2++) {
                    uint32_t b0, b1, b2, b3;
                    ldsm_x4(b0, b1, b2, b3,
                            vsb + 2 * ((16 * j2) * FLDH + bk + 16 * kk + boff));
                    mma_f16(o[2 * j2], pa0, pa1, pa2, pa3, b0, b1);
                    mma_f16(o[2 * j2 + 1], pa0, pa1, pa2, pa3, b2, b3);
                }
            }
            __syncwarp();
        }
    }

    // ---- write O half (feeds proj) in [B,T,NH,HS] ----
    const float inv0 = 1.0f / l0, inv1 = 1.0f / l1;
    const int b_ = hb >> 4, head = hb & 15;
    const int t0 = qt * 128 + 16 * warp + g, t1 = t0 + 8;
    __half* y0 = g_y + (((size_t)(b_ * TT + t0)) * NH_ + head) * HS_;
    __half* y1 = g_y + (((size_t)(b_ * TT + t1)) * NH_ + head) * HS_;
#pragma unroll
    for (int j = 0; j < 8; j++) {
        *(uint32_t*)&y0[8 * j + 2 * tg] = ph2(o[j][0] * inv0, o[j][1] * inv0);
        *(uint32_t*)&y1[8 * j + 2 * tg] = ph2(o[j][2] * inv1, o[j][3] * inv1);
    }
}

// ---------------------------------------------------------------------------
extern "C" void kernel_launch(void* const* d_in, const int* in_sizes, int n_in,
                              void* d_out, int out_size)
{
    const float* x      = (const float*)d_in[0];  // [B,T,C]
    const float* W_attn = (const float*)d_in[1];  // [3C,C]
    const float* W_proj = (const float*)d_in[2];  // [C,C]
    // d_in[3..6] feed a discarded branch — skipped.
    float* out = (float*)d_out;                   // [B,T,C] fp32

    cudaFuncSetAttribute(flash_f16_kernel,
                         cudaFuncAttributeMaxDynamicSharedMemorySize, FLASH_SMEM);

    gemm_f16_kernel<0><<<dim3(3 * CC / 128, BB * TT / 128), 512>>>(x, W_attn, nullptr);
    flash_f16_kernel<<<dim3(TT / 128, HB_), 256, FLASH_SMEM>>>();
    gemm_f16_kernel<1><<<dim3(CC / 128, BB * TT / 128), 512>>>(x, W_proj, out);
}